// round 12
// baseline (speedup 1.0000x reference)
#include <cuda_runtime.h>

// FullPairwise (non-PBC): output layout (float32), MP = M*P:
//   [0      , 2*MP) : atom_index12   out[r*MP + m*P + p] = (r? j : i) + m*N
//   [2*MP   , 5*MP) : shift_values   zeros
//   [5*MP   , 6*MP) : mask           1.0f if d2 <= 5.2^2 else 0.0f
// Total = 6*MP floats = 201 MB -> all offsets fit in uint32.
//
// Compute mapping: lane l of a warp handles pairs wbase + 32k + l (k=0..7)
//   -> coordinate loads have 1-atom lane stride (coalesced-ish, 3-4 lines/LDG)
// Store mapping: via per-warp smem transpose back to contiguous float4 spans
//   -> all global stores remain STG.128, warp-contiguous, __stcs.
static constexpr int      NA = 2048;
static constexpr int      NM = 4;
static constexpr unsigned PP = (unsigned)NA * (NA - 1) / 2;   // 2,096,128 (= 8188*256)
static constexpr unsigned MP = (unsigned)NM * PP;             // 8,384,512

static constexpr int      THREADS       = 256;
static constexpr int      PAIR_BLOCKS   = 1024;               // per molecule
static constexpr unsigned WARPS_PER_MOL = PP / 256u;          // 8188 (exact)
static constexpr unsigned ZERO_F4       = 3 * MP / 4;         // 6,288,384 float4

__device__ __forceinline__ int cumrow(int i) {
    return i * (NA - 1) - ((i * (i - 1)) >> 1);
}

__global__ void __launch_bounds__(256)
fullpair_kernel(const float* __restrict__ coords,   // [NM, NA, 3] AoS
                float* __restrict__ out)
{
    const unsigned bid = blockIdx.x;                  // 0 .. NM*PAIR_BLOCKS-1

    // ---- zero-fill share: block writes f4 span [bid*1536, +1536) ----
    {
        const unsigned zbase = bid * (6u * THREADS);
        float4* zp = (float4*)(out + 2u * MP);
        const float4 z = make_float4(0.f, 0.f, 0.f, 0.f);
        #pragma unroll
        for (int k = 0; k < 6; ++k) {
            unsigned idx = zbase + (unsigned)k * THREADS + threadIdx.x;
            if (idx < ZERO_F4)
                __stcs(zp + idx, z);
        }
    }

    // ---- pair share ----
    const int      m    = bid >> 10;                  // / PAIR_BLOCKS
    const int      pb   = bid & 1023;
    const unsigned wblk = threadIdx.x >> 5;           // warp in block (0..7)
    const unsigned lane = threadIdx.x & 31;
    const unsigned wmol = (unsigned)pb * 8u + wblk;   // warp within molecule
    if (wmol >= WARPS_PER_MOL) return;                // warp-uniform exit
    const unsigned wbase = wmol * 256u;               // first pair of this warp

    // triangular inversion for p = wbase + lane (fp32 exact: operands < 2^24)
    unsigned p = wbase + lane;
    float disc = (float)(16769025u - 8u * p);         // 4095^2 - 8p
    int i = (int)((4095.0f - sqrtf(disc)) * 0.5f);
    if (i < 0) i = 0;
    if (i > NA - 2) i = NA - 2;
    while (cumrow(i + 1) <= (int)p) ++i;
    while (cumrow(i) > (int)p) --i;
    int j = (int)p - cumrow(i) + i + 1;

    __shared__ float4 sbuf[8][3][64];                 // per-warp staging (24 KB)
    float* si = (float*)sbuf[wblk][0];
    float* sj = (float*)sbuf[wblk][1];
    float* sk = (float*)sbuf[wblk][2];

    const float c2  = 5.2f * 5.2f;
    const float off = (float)(m * NA);
    const float* __restrict__ cm = coords + (unsigned)m * (NA * 3);

    float cix = 0.f, ciy = 0.f, ciz = 0.f;
    int cached_i = -1;

    #pragma unroll
    for (int k = 0; k < 8; ++k) {
        si[k * 32 + lane] = (float)i + off;
        sj[k * 32 + lane] = (float)j + off;
        if (i != cached_i) {
            const float* ci = cm + i * 3;
            cix = ci[0]; ciy = ci[1]; ciz = ci[2];
            cached_i = i;
        }
        const float* cj = cm + j * 3;
        float dx = __fsub_rn(cix, cj[0]);
        float dy = __fsub_rn(ciy, cj[1]);
        float dz = __fsub_rn(ciz, cj[2]);
        // same association order as jnp.sum axis -1: (x+y)+z, no fma
        float d2 = __fadd_rn(__fadd_rn(__fmul_rn(dx, dx), __fmul_rn(dy, dy)),
                             __fmul_rn(dz, dz));
        sk[k * 32 + lane] = (d2 <= c2) ? 1.0f : 0.0f;
        if (k < 7) {
            j += 32;
            while (j >= NA) { j = j - NA + i + 2; ++i; }
        }
    }
    __syncwarp();

    const unsigned base_i = (unsigned)m * PP + wbase;    // index row 0
    const unsigned base_j = base_i + MP;                 // index row 1
    const unsigned base_k = base_i + 5u * MP;            // mask

    __stcs((float4*)(out + base_i) + lane,        sbuf[wblk][0][lane]);
    __stcs((float4*)(out + base_i) + 32 + lane,   sbuf[wblk][0][32 + lane]);
    __stcs((float4*)(out + base_j) + lane,        sbuf[wblk][1][lane]);
    __stcs((float4*)(out + base_j) + 32 + lane,   sbuf[wblk][1][32 + lane]);
    __stcs((float4*)(out + base_k) + lane,        sbuf[wblk][2][lane]);
    __stcs((float4*)(out + base_k) + 32 + lane,   sbuf[wblk][2][32 + lane]);
}

extern "C" void kernel_launch(void* const* d_in, const int* in_sizes, int n_in,
                              void* d_out, int out_size) {
    // inputs per metadata order: species(int32), coordinates(f32), cell(f32), pbc(bool)
    const float* coords = (const float*)d_in[1];
    float* out = (float*)d_out;

    fullpair_kernel<<<NM * PAIR_BLOCKS, THREADS>>>(coords, out);
}

// round 14
// speedup vs baseline: 1.0322x; 1.0322x over previous
#include <cuda_runtime.h>

// FullPairwise (non-PBC): output layout (float32), MP = M*P:
//   [0      , 2*MP) : atom_index12   out[r*MP + m*P + p] = (r? j : i) + m*N
//   [2*MP   , 5*MP) : shift_values   zeros
//   [5*MP   , 6*MP) : mask           1.0f if d2 <= 5.2^2 else 0.0f
// Total = 6*MP floats = 201 MB -> all offsets fit in uint32.
//
// Fused, fine-grained design: grid = NM*2047 = 8188 uniform blocks.
// Each thread: 1 quad (4 pairs -> 3 STG.128) + 3 zero float4 (3 STG.128).
// 8188 jobs over 1184 concurrent slots (148 SM x occ 8) -> makespan 7 vs
// 6.92 ideal (~1% quantization, vs ~15% at 4096-block granularity).
// Zero region = 6,288,384 f4 = 8188 * 768 exactly -> no guard needed.
static constexpr int      NA = 2048;
static constexpr int      NM = 4;
static constexpr unsigned PP = (unsigned)NA * (NA - 1) / 2;   // 2,096,128
static constexpr unsigned MP = (unsigned)NM * PP;             // 8,384,512

static constexpr int      THREADS     = 256;
static constexpr unsigned QUADS       = PP / 4;               // 524,032 = 2047*256 exact
static constexpr int      PAIR_BLOCKS = 2047;                 // per molecule
static constexpr int      GRID        = NM * PAIR_BLOCKS;     // 8188
static constexpr unsigned ZERO_F4     = 3 * MP / 4;           // 6,288,384 = 8188*768

__device__ __forceinline__ int cumrow(int i) {
    return i * (NA - 1) - ((i * (i - 1)) >> 1);
}

__global__ void __launch_bounds__(256)
fullpair_kernel(const float* __restrict__ coords,   // [NM, NA, 3] AoS
                float* __restrict__ out)
{
    const unsigned bid = blockIdx.x;                  // 0 .. 8187

    // ---- zero share: block writes f4 span [bid*768, bid*768+768), exact ----
    {
        const unsigned zbase = bid * 768u;
        float4* zp = (float4*)(out + 2u * MP);
        const float4 z = make_float4(0.f, 0.f, 0.f, 0.f);
        #pragma unroll
        for (int k = 0; k < 3; ++k)
            __stcs(zp + zbase + (unsigned)k * THREADS + threadIdx.x, z);
    }

    // ---- pair share: one thread = 4 consecutive pairs of one molecule ----
    const unsigned m  = bid / (unsigned)PAIR_BLOCKS;
    const unsigned pb = bid - m * PAIR_BLOCKS;
    const unsigned p0 = (pb * THREADS + threadIdx.x) * 4u;   // < PP always (exact)

    // fp32 triangular inversion (operands < 2^24, exact), exact int correction
    float disc = (float)(16769025u - 8u * p0);        // 4095^2 - 8p
    int i = (int)((4095.0f - sqrtf(disc)) * 0.5f);
    if (i < 0) i = 0;
    if (i > NA - 2) i = NA - 2;
    while (cumrow(i + 1) <= (int)p0) ++i;
    while (cumrow(i) > (int)p0) --i;
    int j = (int)p0 - cumrow(i) + i + 1;

    const float c2  = 5.2f * 5.2f;
    const float off = (float)(m * NA);
    const float* __restrict__ cm = coords + m * (NA * 3);

    float iv[4], jv[4], mk[4];
    float cix = 0.f, ciy = 0.f, ciz = 0.f;
    int cached_i = -1;
    int ii = i, jj = j;
    #pragma unroll
    for (int k = 0; k < 4; ++k) {
        iv[k] = (float)ii + off;
        jv[k] = (float)jj + off;
        if (ii != cached_i) {
            const float* ci = cm + ii * 3;
            cix = ci[0]; ciy = ci[1]; ciz = ci[2];
            cached_i = ii;
        }
        const float* cj = cm + jj * 3;
        float dx = __fsub_rn(cix, cj[0]);
        float dy = __fsub_rn(ciy, cj[1]);
        float dz = __fsub_rn(ciz, cj[2]);
        // same association order as jnp.sum axis -1: (x+y)+z, no fma
        float d2 = __fadd_rn(__fadd_rn(__fmul_rn(dx, dx), __fmul_rn(dy, dy)),
                             __fmul_rn(dz, dz));
        mk[k] = (d2 <= c2) ? 1.0f : 0.0f;
        ++jj;
        if (jj >= NA) { ++ii; jj = ii + 1; }
    }

    const unsigned base_i = m * PP + p0;                 // index row 0
    const unsigned base_j = base_i + MP;                 // index row 1
    const unsigned base_k = base_i + 5u * MP;            // mask

    __stcs((float4*)(out + base_i), make_float4(iv[0], iv[1], iv[2], iv[3]));
    __stcs((float4*)(out + base_j), make_float4(jv[0], jv[1], jv[2], jv[3]));
    __stcs((float4*)(out + base_k), make_float4(mk[0], mk[1], mk[2], mk[3]));
}

extern "C" void kernel_launch(void* const* d_in, const int* in_sizes, int n_in,
                              void* d_out, int out_size) {
    // inputs per metadata order: species(int32), coordinates(f32), cell(f32), pbc(bool)
    const float* coords = (const float*)d_in[1];
    float* out = (float*)d_out;

    fullpair_kernel<<<GRID, THREADS>>>(coords, out);
}